// round 2
// baseline (speedup 1.0000x reference)
#include <cuda_runtime.h>
#include <math.h>

// iNGPDW: fused hash-grid encode + erf scaling + 40->64->64->13 SELU MLP.
// Two threads per point (lane pair). Each thread encodes 5 of 10 levels and
// computes 32 of 64 hidden units per layer; partner activations are exchanged
// via shfl.xor inside the unrolled k-loop. MLP accumulation uses packed
// fma.rn.f32x2 (sm_103a FFMA2) -> half the FMA instruction count.

constexpr int NLEV = 10;
constexpr int TBL  = 1 << 16;
constexpr int HIDN = 64;
constexpr int OUTD = 13;

struct ResParams { int res[NLEV]; };

typedef unsigned long long u64;

__device__ __forceinline__ u64 pk2(float lo, float hi) {
    u64 r; asm("mov.b64 %0, {%1, %2};" : "=l"(r) : "f"(lo), "f"(hi)); return r;
}
__device__ __forceinline__ u64 dup2(float v) {
    u64 r; asm("mov.b64 %0, {%1, %1};" : "=l"(r) : "f"(v)); return r;
}
__device__ __forceinline__ void upk2(u64 v, float& lo, float& hi) {
    asm("mov.b64 {%0, %1}, %2;" : "=f"(lo), "=f"(hi) : "l"(v));
}
__device__ __forceinline__ void fma2(u64& acc, u64 a, u64 b) {
    asm("fma.rn.f32x2 %0, %1, %2, %0;" : "+l"(acc) : "l"(a), "l"(b));
}

__device__ __forceinline__ float selu_f(float v) {
    const float sc = 1.0507009873554805f;
    const float al = 1.6732632423543772f;
    return v > 0.0f ? sc * v : sc * (al * expm1f(v));
}

__global__ __launch_bounds__(256, 3)
void ngp_fused2_kernel(const float*  __restrict__ gx,     // [N,3]
                       const float*  __restrict__ gcr,    // [N]
                       const float4* __restrict__ gtab,   // [NLEV*TBL] float4
                       const float*  __restrict__ gW1,    // [40,64]
                       const float*  __restrict__ gb1,    // [64]
                       const float*  __restrict__ gW2,    // [64,64]
                       const float*  __restrict__ gb2,    // [64]
                       const float*  __restrict__ gW3,    // [64,13]
                       const float*  __restrict__ gb3,    // [13]
                       float*        __restrict__ gout,   // [N,13]
                       int N, ResParams rp)
{
    // Weights stay in NATURAL [k][j] layout (j contiguous -> packed j-pairs).
    __shared__ float sW1[40 * HIDN];       // 10240 B
    __shared__ float sW2[HIDN * HIDN];     // 16384 B
    __shared__ float sW3[HIDN * 16];       // 4096 B (rows padded 13 -> 16)
    __shared__ float sB1[HIDN];
    __shared__ float sB2[HIDN];
    __shared__ float sB3[16];

    const int tid = threadIdx.x;
    for (int i = tid; i < 40 * HIDN; i += blockDim.x) sW1[i] = gW1[i];
    for (int i = tid; i < HIDN * HIDN; i += blockDim.x) sW2[i] = gW2[i];
    for (int i = tid; i < HIDN * 16; i += blockDim.x) {
        int k = i >> 4, j = i & 15;
        sW3[i] = (j < OUTD) ? gW3[k * OUTD + j] : 0.0f;
    }
    if (tid < HIDN) { sB1[tid] = gb1[tid]; sB2[tid] = gb2[tid]; }
    if (tid < 16)   { sB3[tid] = (tid < OUTD) ? gb3[tid] : 0.0f; }
    __syncthreads();

    const int gt = blockIdx.x * blockDim.x + tid;
    const int n_raw = gt >> 1;          // point index
    const int p = gt & 1;               // half: 0 -> levels 0-4 / j 0-31, 1 -> levels 5-9 / j 32-63
    const bool valid = (n_raw < N);
    const int n = valid ? n_raw : (N - 1);   // clamp; keep all lanes alive for shfl

    const float x0 = gx[3 * n + 0];
    const float x1 = gx[3 * n + 1];
    const float x2 = gx[3 * n + 2];
    const float crs = gcr[n] * 0.5f;    // SCALE_MULTI

    // ---- encoding: this thread's 5 levels -> h_local[20], index i = d*5 + lo,
    //      global feature k = d*10 + p*5 + lo ----
    float h_local[20];
    const int lvl0 = p * 5;
    #pragma unroll
    for (int lo = 0; lo < 5; lo++) {
        const int l = lvl0 + lo;
        const float rf = (float)rp.res[l];
        const float xs0 = x0 * rf, xs1 = x1 * rf, xs2 = x2 * rf;
        const float fb0 = floorf(xs0), fb1 = floorf(xs1), fb2 = floorf(xs2);
        const float f0 = xs0 - fb0, f1 = xs1 - fb1, f2 = xs2 - fb2;
        const float g0 = 1.0f - f0, g1 = 1.0f - f1, g2 = 1.0f - f2;
        const unsigned c0 = (unsigned)fb0, c1 = (unsigned)fb1, c2 = (unsigned)fb2;

        float a0 = 0.f, a1 = 0.f, a2 = 0.f, a3 = 0.f;
        #pragma unroll
        for (int c = 0; c < 8; c++) {
            const unsigned ox = (c >> 2) & 1u, oy = (c >> 1) & 1u, oz = c & 1u;
            unsigned hsh = (c0 + ox)
                         ^ ((c1 + oy) * 2654435761u)
                         ^ ((c2 + oz) * 805459861u);
            const unsigned idx = hsh & (unsigned)(TBL - 1);
            const float4 t = __ldg(&gtab[(unsigned)(l * TBL) + idx]);
            const float w = (ox ? f0 : g0) * (oy ? f1 : g1) * (oz ? f2 : g2);
            a0 = fmaf(w, t.x, a0);
            a1 = fmaf(w, t.y, a1);
            a2 = fmaf(w, t.z, a2);
            a3 = fmaf(w, t.w, a3);
        }
        const float denom = fmaxf((8.0f * (float)l) * crs, 1e-12f);
        const float scal = erff(rsqrtf(denom));
        h_local[0 * 5 + lo] = a0 * scal;
        h_local[1 * 5 + lo] = a1 * scal;
        h_local[2 * 5 + lo] = a2 * scal;
        h_local[3 * 5 + lo] = a3 * scal;
    }

    // ---- layer 1: 40 -> 64, SELU. This thread computes j = p*32 .. p*32+31
    //      in two passes of 16 (8 packed accumulators each). ----
    float a_local[32];
    #pragma unroll
    for (int pass = 0; pass < 2; pass++) {
        const int jbase = p * 32 + pass * 16;
        u64 acc[8];
        #pragma unroll
        for (int q = 0; q < 8; q++)
            acc[q] = pk2(sB1[jbase + 2 * q], sB1[jbase + 2 * q + 1]);

        #pragma unroll
        for (int i = 0; i < 20; i++) {
            const int d = i / 5, lo = i - d * 5;
            const int k_lo = d * 10 + lo;        // owned by p=0
            const int k_hi = d * 10 + 5 + lo;    // owned by p=1
            const float mine = h_local[i];
            const float exch = __shfl_xor_sync(0xffffffffu, mine, 1);
            const float vlo = (p == 0) ? mine : exch;
            const float vhi = (p == 0) ? exch : mine;
            const u64 dlo = dup2(vlo), dhi = dup2(vhi);
            const ulonglong2* r0 = reinterpret_cast<const ulonglong2*>(&sW1[k_lo * HIDN + jbase]);
            const ulonglong2* r1 = reinterpret_cast<const ulonglong2*>(&sW1[k_hi * HIDN + jbase]);
            #pragma unroll
            for (int q4 = 0; q4 < 4; q4++) {
                const ulonglong2 w0 = r0[q4];
                const ulonglong2 w1 = r1[q4];
                fma2(acc[2 * q4 + 0], dlo, w0.x);
                fma2(acc[2 * q4 + 1], dlo, w0.y);
                fma2(acc[2 * q4 + 0], dhi, w1.x);
                fma2(acc[2 * q4 + 1], dhi, w1.y);
            }
        }
        #pragma unroll
        for (int q = 0; q < 8; q++) {
            float s0, s1; upk2(acc[q], s0, s1);
            a_local[pass * 16 + 2 * q + 0] = selu_f(s0);
            a_local[pass * 16 + 2 * q + 1] = selu_f(s1);
        }
    }

    // ---- layer 2: 64 -> 64, SELU. Own k = p*32 + m; exchange partner's. ----
    float b_local[32];
    #pragma unroll
    for (int pass = 0; pass < 2; pass++) {
        const int jbase = p * 32 + pass * 16;
        u64 acc[8];
        #pragma unroll
        for (int q = 0; q < 8; q++)
            acc[q] = pk2(sB2[jbase + 2 * q], sB2[jbase + 2 * q + 1]);

        #pragma unroll
        for (int m = 0; m < 32; m++) {
            const int k_lo = m;          // owned by p=0
            const int k_hi = 32 + m;     // owned by p=1
            const float mine = a_local[m];
            const float exch = __shfl_xor_sync(0xffffffffu, mine, 1);
            const float vlo = (p == 0) ? mine : exch;
            const float vhi = (p == 0) ? exch : mine;
            const u64 dlo = dup2(vlo), dhi = dup2(vhi);
            const ulonglong2* r0 = reinterpret_cast<const ulonglong2*>(&sW2[k_lo * HIDN + jbase]);
            const ulonglong2* r1 = reinterpret_cast<const ulonglong2*>(&sW2[k_hi * HIDN + jbase]);
            #pragma unroll
            for (int q4 = 0; q4 < 4; q4++) {
                const ulonglong2 w0 = r0[q4];
                const ulonglong2 w1 = r1[q4];
                fma2(acc[2 * q4 + 0], dlo, w0.x);
                fma2(acc[2 * q4 + 1], dlo, w0.y);
                fma2(acc[2 * q4 + 0], dhi, w1.x);
                fma2(acc[2 * q4 + 1], dhi, w1.y);
            }
        }
        #pragma unroll
        for (int q = 0; q < 8; q++) {
            float s0, s1; upk2(acc[q], s0, s1);
            b_local[pass * 16 + 2 * q + 0] = selu_f(s0);
            b_local[pass * 16 + 2 * q + 1] = selu_f(s1);
        }
    }

    // ---- layer 3: 64 -> 13. Partial sums over OWN 32 k, then one xor-add. ----
    u64 acc3[7];
    #pragma unroll
    for (int q = 0; q < 7; q++)
        acc3[q] = pk2(sB3[2 * q] * 0.5f, sB3[2 * q + 1] * 0.5f);  // bias split across pair
    #pragma unroll
    for (int m = 0; m < 32; m++) {
        const int k = p * 32 + m;
        const u64 dv = dup2(b_local[m]);
        const u64* row = reinterpret_cast<const u64*>(&sW3[k * 16]);
        #pragma unroll
        for (int q = 0; q < 7; q++) fma2(acc3[q], dv, row[q]);
    }
    float s[14];
    #pragma unroll
    for (int q = 0; q < 7; q++) upk2(acc3[q], s[2 * q], s[2 * q + 1]);
    #pragma unroll
    for (int j = 0; j < 13; j++)
        s[j] += __shfl_xor_sync(0xffffffffu, s[j], 1);

    if (valid) {
        float* op = gout + (size_t)n * OUTD;
        if (p == 0) {
            #pragma unroll
            for (int j = 0; j < 7; j++) op[j] = s[j];
        } else {
            #pragma unroll
            for (int j = 7; j < 13; j++) op[j] = s[j];
        }
    }
}

extern "C" void kernel_launch(void* const* d_in, const int* in_sizes, int n_in,
                              void* d_out, int out_size) {
    const float*  x   = (const float*)d_in[0];
    const float*  cr  = (const float*)d_in[1];
    const float4* tab = (const float4*)d_in[2];
    const float*  W1  = (const float*)d_in[3];
    const float*  b1  = (const float*)d_in[4];
    const float*  W2  = (const float*)d_in[5];
    const float*  b2  = (const float*)d_in[6];
    const float*  W3  = (const float*)d_in[7];
    const float*  b3  = (const float*)d_in[8];
    float* out = (float*)d_out;

    const int N = in_sizes[0] / 3;

    // Reference resolutions, identical libm double sequence.
    ResParams rp;
    const double B = exp((log(16.0 * pow(2.0, 10.0)) - log(16.0)) / 9.0);
    for (int l = 0; l < NLEV; l++) {
        rp.res[l] = (int)floor(16.0 * pow(B, (double)l));
    }

    const int threads = 256;
    const long long totalThreads = 2LL * N;
    const int blocks = (int)((totalThreads + threads - 1) / threads);
    ngp_fused2_kernel<<<blocks, threads>>>(x, cr, tab, W1, b1, W2, b2, W3, b3,
                                           out, N, rp);
}

// round 4
// speedup vs baseline: 1.2433x; 1.2433x over previous
#include <cuda_runtime.h>
#include <math.h>

// iNGPDW: fused hash-grid encode + erf scaling + 40->64->64->13 SELU MLP.
// One thread per point. MLP uses packed fma.rn.f32x2 (j-pairs) to halve FMA
// instruction count; layer-1 activations staged in shared memory (private
// per-thread column, no barrier) to eliminate register spills.
// SELU uses expm1f (NOT __expf(v)-1: catastrophic cancellation for the tiny
// pre-activations this net produces -> rel_err 1.3e-3, seen in round 3).

constexpr int NLEV = 10;
constexpr int TBL  = 1 << 16;
constexpr int HIDN = 64;
constexpr int OUTD = 13;
constexpr int BLK  = 256;

struct ResParams { int res[NLEV]; };

typedef unsigned long long u64;

__device__ __forceinline__ u64 dup2(float v) {
    u64 r; asm("mov.b64 %0, {%1, %1};" : "=l"(r) : "f"(v)); return r;
}
__device__ __forceinline__ void upk2(u64 v, float& lo, float& hi) {
    asm("mov.b64 {%0, %1}, %2;" : "=f"(lo), "=f"(hi) : "l"(v));
}
__device__ __forceinline__ void fma2(u64& acc, u64 a, u64 b) {
    asm("fma.rn.f32x2 %0, %1, %2, %0;" : "+l"(acc) : "l"(a), "l"(b));
}

__device__ __forceinline__ float selu_f(float v) {
    const float sc = 1.0507009873554805f;
    const float al = 1.6732632423543772f;
    return v > 0.0f ? sc * v : sc * (al * expm1f(v));
}

__global__ __launch_bounds__(BLK, 2)
void ngp_fused4_kernel(const float*  __restrict__ gx,     // [N,3]
                       const float*  __restrict__ gcr,    // [N]
                       const float4* __restrict__ gtab,   // [NLEV*TBL] float4
                       const float*  __restrict__ gW1,    // [40,64]
                       const float*  __restrict__ gb1,    // [64]
                       const float*  __restrict__ gW2,    // [64,64]
                       const float*  __restrict__ gb2,    // [64]
                       const float*  __restrict__ gW3,    // [64,13]
                       const float*  __restrict__ gb3,    // [13]
                       float*        __restrict__ gout,   // [N,13]
                       int N, ResParams rp)
{
    // Weights in natural [k][j] layout (j contiguous -> packed j-pairs).
    __shared__ float sW1[40 * HIDN];      // 10240 B
    __shared__ float sW2[HIDN * HIDN];    // 16384 B
    __shared__ float sW3[HIDN * 16];      // 4096 B (rows padded 13 -> 16)
    __shared__ float sB1[HIDN];
    __shared__ float sB2[HIDN];
    __shared__ float sB3[16];
    extern __shared__ float sA[];         // [HIDN][BLK] = 64 KB, per-thread column

    const int tid = threadIdx.x;
    for (int i = tid; i < 40 * HIDN; i += BLK) sW1[i] = gW1[i];
    for (int i = tid; i < HIDN * HIDN; i += BLK) sW2[i] = gW2[i];
    for (int i = tid; i < HIDN * 16; i += BLK) {
        int k = i >> 4, j = i & 15;
        sW3[i] = (j < OUTD) ? gW3[k * OUTD + j] : 0.0f;
    }
    if (tid < HIDN) { sB1[tid] = gb1[tid]; sB2[tid] = gb2[tid]; }
    if (tid < 16)   { sB3[tid] = (tid < OUTD) ? gb3[tid] : 0.0f; }
    __syncthreads();

    const int n = blockIdx.x * BLK + tid;
    if (n >= N) return;

    const float x0 = gx[3 * n + 0];
    const float x1 = gx[3 * n + 1];
    const float x2 = gx[3 * n + 2];
    const float crs = gcr[n] * 0.5f;      // SCALE_MULTI

    // ---- hash-grid encoding + erf scaling ----
    float h[40];                          // h[d*10 + l]
    #pragma unroll
    for (int l = 0; l < NLEV; l++) {
        const float rf = (float)rp.res[l];
        const float xs0 = x0 * rf, xs1 = x1 * rf, xs2 = x2 * rf;
        const float fb0 = floorf(xs0), fb1 = floorf(xs1), fb2 = floorf(xs2);
        const float f0 = xs0 - fb0, f1 = xs1 - fb1, f2 = xs2 - fb2;
        const float g0 = 1.0f - f0, g1 = 1.0f - f1, g2 = 1.0f - f2;
        const unsigned c0 = (unsigned)fb0, c1 = (unsigned)fb1, c2 = (unsigned)fb2;

        // precomputed hash partials
        const unsigned hx0 = c0,               hx1 = c0 + 1u;
        const unsigned hy0 = c1 * 2654435761u, hy1 = hy0 + 2654435761u;
        const unsigned hz0 = c2 * 805459861u,  hz1 = hz0 + 805459861u;
        // precomputed yz weight products
        const float wyz00 = g1 * g2, wyz01 = g1 * f2;
        const float wyz10 = f1 * g2, wyz11 = f1 * f2;

        const float4* tb = gtab + (unsigned)(l * TBL);
        float a0 = 0.f, a1 = 0.f, a2 = 0.f, a3 = 0.f;
        #pragma unroll
        for (int c = 0; c < 8; c++) {
            const unsigned hx = (c & 4) ? hx1 : hx0;
            const unsigned hy = (c & 2) ? hy1 : hy0;
            const unsigned hz = (c & 1) ? hz1 : hz0;
            const unsigned idx = (hx ^ hy ^ hz) & (unsigned)(TBL - 1);
            const float4 t = __ldg(&tb[idx]);
            const float wyz = (c & 2) ? ((c & 1) ? wyz11 : wyz10)
                                      : ((c & 1) ? wyz01 : wyz00);
            const float w = ((c & 4) ? f0 : g0) * wyz;
            a0 = fmaf(w, t.x, a0);
            a1 = fmaf(w, t.y, a1);
            a2 = fmaf(w, t.z, a2);
            a3 = fmaf(w, t.w, a3);
        }
        float scal;
        if (l == 0) {
            scal = 1.0f;  // erf(1/sqrt(1e-12)) == 1 in fp32
        } else {
            const float denom = fmaxf((8.0f * (float)l) * crs, 1e-12f);
            scal = erff(rsqrtf(denom));
        }
        h[0 * 10 + l] = a0 * scal;
        h[1 * 10 + l] = a1 * scal;
        h[2 * 10 + l] = a2 * scal;
        h[3 * 10 + l] = a3 * scal;
    }

    // ---- layer 1: 40 -> 64, SELU; results staged to sA (private column) ----
    #pragma unroll
    for (int half = 0; half < 2; half++) {
        const int jb = half * 32;
        u64 acc[16];
        const u64* bi = reinterpret_cast<const u64*>(&sB1[jb]);
        #pragma unroll
        for (int q = 0; q < 16; q++) acc[q] = bi[q];

        #pragma unroll
        for (int k = 0; k < 40; k++) {
            const u64 d = dup2(h[k]);
            const ulonglong2* wr = reinterpret_cast<const ulonglong2*>(&sW1[k * HIDN + jb]);
            #pragma unroll
            for (int q2 = 0; q2 < 8; q2++) {
                const ulonglong2 w = wr[q2];
                fma2(acc[2 * q2 + 0], d, w.x);
                fma2(acc[2 * q2 + 1], d, w.y);
            }
        }
        #pragma unroll
        for (int q = 0; q < 16; q++) {
            float s0, s1; upk2(acc[q], s0, s1);
            sA[(jb + 2 * q + 0) * BLK + tid] = selu_f(s0);
            sA[(jb + 2 * q + 1) * BLK + tid] = selu_f(s1);
        }
    }
    // no barrier needed: each thread reads only its own column of sA

    // ---- layer 2: 64 -> 64, SELU; b kept in registers ----
    float bct[HIDN];
    #pragma unroll
    for (int half = 0; half < 2; half++) {
        const int jb = half * 32;
        u64 acc[16];
        const u64* bi = reinterpret_cast<const u64*>(&sB2[jb]);
        #pragma unroll
        for (int q = 0; q < 16; q++) acc[q] = bi[q];

        #pragma unroll
        for (int k = 0; k < HIDN; k++) {
            const float av = sA[k * BLK + tid];
            const u64 d = dup2(av);
            const ulonglong2* wr = reinterpret_cast<const ulonglong2*>(&sW2[k * HIDN + jb]);
            #pragma unroll
            for (int q2 = 0; q2 < 8; q2++) {
                const ulonglong2 w = wr[q2];
                fma2(acc[2 * q2 + 0], d, w.x);
                fma2(acc[2 * q2 + 1], d, w.y);
            }
        }
        #pragma unroll
        for (int q = 0; q < 16; q++) {
            float s0, s1; upk2(acc[q], s0, s1);
            bct[jb + 2 * q + 0] = selu_f(s0);
            bct[jb + 2 * q + 1] = selu_f(s1);
        }
    }

    // ---- layer 3: 64 -> 13, linear ----
    u64 acc3[7];
    const u64* bi3 = reinterpret_cast<const u64*>(&sB3[0]);
    #pragma unroll
    for (int q = 0; q < 7; q++) acc3[q] = bi3[q];
    #pragma unroll
    for (int k = 0; k < HIDN; k++) {
        const u64 d = dup2(bct[k]);
        const ulonglong2* wr = reinterpret_cast<const ulonglong2*>(&sW3[k * 16]);
        #pragma unroll
        for (int q2 = 0; q2 < 4; q2++) {
            const ulonglong2 w = wr[q2];
            fma2(acc3[2 * q2 + 0], d, w.x);
            if (q2 < 3) fma2(acc3[2 * q2 + 1], d, w.y);
        }
    }
    float s[14];
    #pragma unroll
    for (int q = 0; q < 7; q++) upk2(acc3[q], s[2 * q], s[2 * q + 1]);

    float* op = gout + (size_t)n * OUTD;
    #pragma unroll
    for (int j = 0; j < OUTD; j++) op[j] = s[j];
}

extern "C" void kernel_launch(void* const* d_in, const int* in_sizes, int n_in,
                              void* d_out, int out_size) {
    const float*  x   = (const float*)d_in[0];
    const float*  cr  = (const float*)d_in[1];
    const float4* tab = (const float4*)d_in[2];
    const float*  W1  = (const float*)d_in[3];
    const float*  b1  = (const float*)d_in[4];
    const float*  W2  = (const float*)d_in[5];
    const float*  b2  = (const float*)d_in[6];
    const float*  W3  = (const float*)d_in[7];
    const float*  b3  = (const float*)d_in[8];
    float* out = (float*)d_out;

    const int N = in_sizes[0] / 3;

    // Reference resolutions, identical libm double sequence.
    ResParams rp;
    const double B = exp((log(16.0 * pow(2.0, 10.0)) - log(16.0)) / 9.0);
    for (int l = 0; l < NLEV; l++) {
        rp.res[l] = (int)floor(16.0 * pow(B, (double)l));
    }

    static bool attr_set = false;
    if (!attr_set) {
        cudaFuncSetAttribute(ngp_fused4_kernel,
                             cudaFuncAttributeMaxDynamicSharedMemorySize,
                             HIDN * BLK * (int)sizeof(float));
        attr_set = true;
    }

    const int blocks = (N + BLK - 1) / BLK;
    ngp_fused4_kernel<<<blocks, BLK, HIDN * BLK * sizeof(float)>>>(
        x, cr, tab, W1, b1, W2, b2, W3, b3, out, N, rp);
}